// round 1
// baseline (speedup 1.0000x reference)
#include <cuda_runtime.h>
#include <math.h>

#define D_MODEL 32
#define NHEAD 4
#define DH 8
#define WIN 256
#define DFF 64
#define INDIM 58
#define HOUT 25
#define NLAYER 4

// ---- shared memory layout (floats) ----
// layer-weight buffer (also overlaid with embedding / head weights)
#define L_IPW  0      // 96*32
#define L_IPB  3072   // 96
#define L_OPW  3168   // 32*32
#define L_OPB  4192   // 32
#define L_G1   4224
#define L_B1   4256
#define L_W1   4288   // 64*32
#define L_BB1  6336   // 64
#define L_W2T  6400   // 64*32 (transposed lin2_w)
#define L_BB2  8448
#define L_G2   8480
#define L_B2   8512
#define W_FLOATS 8544

// embedding overlay
#define E_FPW  0      // 32*58
#define E_FPB  1856
#define E_LEMB 1888   // 12*32
#define E_FB   2272   // 3*16

// head overlay
#define H_NOG  0
#define H_NOB  32
#define H_HW   64     // 25*32
#define H_HB   864

#define KV_STRIDE 36           // padded row stride (16B-aligned, 4-way write conflict)
#define OFF_K  8544
#define OFF_V  (OFF_K + WIN*KV_STRIDE)    // 8544 + 9216 = 17760
#define SMEM_FLOATS (OFF_V + WIN*KV_STRIDE)  // 26976
#define SMEM_BYTES (SMEM_FLOATS * 4)         // 107904

__device__ __forceinline__ float dot32(const float* __restrict__ w, const float h[D_MODEL]) {
    float a0 = 0.f, a1 = 0.f, a2 = 0.f, a3 = 0.f;
#pragma unroll
    for (int i = 0; i < 8; i++) {
        float4 wv = *reinterpret_cast<const float4*>(w + 4 * i);
        a0 = fmaf(wv.x, h[4 * i + 0], a0);
        a1 = fmaf(wv.y, h[4 * i + 1], a1);
        a2 = fmaf(wv.z, h[4 * i + 2], a2);
        a3 = fmaf(wv.w, h[4 * i + 3], a3);
    }
    return (a0 + a1) + (a2 + a3);
}

__device__ __forceinline__ void ln32(const float v[D_MODEL], const float* __restrict__ g,
                                     const float* __restrict__ b, float outv[D_MODEL]) {
    float m = 0.f;
#pragma unroll
    for (int c = 0; c < D_MODEL; c++) m += v[c];
    m *= 0.03125f;
    float var = 0.f;
#pragma unroll
    for (int c = 0; c < D_MODEL; c++) { float d = v[c] - m; var = fmaf(d, d, var); }
    var *= 0.03125f;
    float inv = rsqrtf(var + 1e-5f);
#pragma unroll
    for (int c = 0; c < D_MODEL; c++) outv[c] = (v[c] - m) * inv * g[c] + b[c];
}

__global__ void __launch_bounds__(256, 2) spai_kernel(
    const float* __restrict__ x, const int* __restrict__ layers,
    const float* __restrict__ fpw, const float* __restrict__ fpb,
    const float* __restrict__ lemb, const float* __restrict__ fB,
    const float* __restrict__ ipw, const float* __restrict__ ipb,
    const float* __restrict__ opw, const float* __restrict__ opb,
    const float* __restrict__ g1, const float* __restrict__ b1,
    const float* __restrict__ w1, const float* __restrict__ bb1,
    const float* __restrict__ w2, const float* __restrict__ bb2,
    const float* __restrict__ g2, const float* __restrict__ b2,
    const float* __restrict__ nog, const float* __restrict__ nob,
    const float* __restrict__ hw, const float* __restrict__ hb,
    float* __restrict__ out)
{
    extern __shared__ float sw[];
    float* ks = sw + OFF_K;
    float* vs = sw + OFF_V;
    const int tid = threadIdx.x;
    const long long g = (long long)blockIdx.x * WIN + tid;

    // ---------------- embedding weights ----------------
    for (int i = tid; i < 32 * INDIM; i += 256) sw[E_FPW + i] = fpw[i];
    if (tid < 32) sw[E_FPB + tid] = fpb[tid];
    for (int i = tid; i < 12 * 32; i += 256) sw[E_LEMB + i] = lemb[i];
    if (tid < 48) sw[E_FB + tid] = fB[tid];
    __syncthreads();

    // ---------------- embedding ----------------
    const float* xp = x + (size_t)g * INDIM;
    const float p0 = xp[0], p1 = xp[1], p2 = xp[2];
    const int lay = layers[g];

    float h[D_MODEL];
#pragma unroll
    for (int c = 0; c < D_MODEL; c++) h[c] = sw[E_FPB + c] + sw[E_LEMB + lay * 32 + c];

#pragma unroll 1
    for (int k = 0; k < INDIM; k++) {
        float xk = __ldg(xp + k);
#pragma unroll
        for (int c = 0; c < D_MODEL; c++) h[c] = fmaf(xk, sw[E_FPW + c * INDIM + k], h[c]);
    }

#pragma unroll
    for (int j = 0; j < 16; j++) {
        float pr = 6.28318530717958647692f *
                   (p0 * sw[E_FB + j] + p1 * sw[E_FB + 16 + j] + p2 * sw[E_FB + 32 + j]);
        float sn, cs;
        sincosf(pr, &sn, &cs);
        h[j] += sn;
        h[j + 16] += cs;
    }

    // ---------------- transformer layers ----------------
    for (int li = 0; li < NLAYER; li++) {
        __syncthreads();
        // cooperative weight load (per layer)
        for (int i = tid; i < 3072; i += 256) sw[L_IPW + i] = ipw[li * 3072 + i];
        if (tid < 96)  sw[L_IPB + tid] = ipb[li * 96 + tid];
        for (int i = tid; i < 1024; i += 256) sw[L_OPW + i] = opw[li * 1024 + i];
        if (tid < 32)  sw[L_OPB + tid] = opb[li * 32 + tid];
        if (tid < 32)  sw[L_G1 + tid] = g1[li * 32 + tid];
        if (tid < 32)  sw[L_B1 + tid] = b1[li * 32 + tid];
        for (int i = tid; i < 2048; i += 256) sw[L_W1 + i] = w1[li * 2048 + i];
        if (tid < 64)  sw[L_BB1 + tid] = bb1[li * 64 + tid];
        for (int i = tid; i < 2048; i += 256) {
            int c = i >> 6, f = i & 63;
            sw[L_W2T + f * 32 + c] = w2[li * 2048 + i];
        }
        if (tid < 32)  sw[L_BB2 + tid] = bb2[li * 32 + tid];
        if (tid < 32)  sw[L_G2 + tid] = g2[li * 32 + tid];
        if (tid < 32)  sw[L_B2 + tid] = b2[li * 32 + tid];
        __syncthreads();

        // ----- QKV -----
        const float rs = 0.35355339059327376220f;  // 1/sqrt(8), folded into q
        float q[D_MODEL];
#pragma unroll
        for (int o = 0; o < 32; o++)
            q[o] = (dot32(sw + L_IPW + o * 32, h) + sw[L_IPB + o]) * rs;
#pragma unroll 1
        for (int o = 32; o < 64; o++)
            ks[tid * KV_STRIDE + (o - 32)] = dot32(sw + L_IPW + o * 32, h) + sw[L_IPB + o];
#pragma unroll 1
        for (int o = 64; o < 96; o++)
            vs[tid * KV_STRIDE + (o - 64)] = dot32(sw + L_IPW + o * 32, h) + sw[L_IPB + o];
        __syncthreads();

        // ----- attention (scores are tiny for this model; exp-sum without max-shift) -----
        float oa[D_MODEL];
#pragma unroll
        for (int c = 0; c < D_MODEL; c++) oa[c] = 0.f;
        float l[NHEAD] = {0.f, 0.f, 0.f, 0.f};

#pragma unroll 2
        for (int j = 0; j < WIN; j++) {
            const float4* kp = reinterpret_cast<const float4*>(ks + j * KV_STRIDE);
            float s[NHEAD];
#pragma unroll
            for (int hh = 0; hh < NHEAD; hh++) {
                float4 ka = kp[2 * hh], kb = kp[2 * hh + 1];
                float a0 = ka.x * q[8 * hh + 0];
                a0 = fmaf(ka.y, q[8 * hh + 1], a0);
                a0 = fmaf(ka.z, q[8 * hh + 2], a0);
                a0 = fmaf(ka.w, q[8 * hh + 3], a0);
                float a1 = kb.x * q[8 * hh + 4];
                a1 = fmaf(kb.y, q[8 * hh + 5], a1);
                a1 = fmaf(kb.z, q[8 * hh + 6], a1);
                a1 = fmaf(kb.w, q[8 * hh + 7], a1);
                s[hh] = a0 + a1;
            }
            float p[NHEAD];
#pragma unroll
            for (int hh = 0; hh < NHEAD; hh++) { p[hh] = __expf(s[hh]); l[hh] += p[hh]; }

            const float4* vp = reinterpret_cast<const float4*>(vs + j * KV_STRIDE);
#pragma unroll
            for (int hh = 0; hh < NHEAD; hh++) {
                float4 va = vp[2 * hh], vb = vp[2 * hh + 1];
                oa[8 * hh + 0] = fmaf(p[hh], va.x, oa[8 * hh + 0]);
                oa[8 * hh + 1] = fmaf(p[hh], va.y, oa[8 * hh + 1]);
                oa[8 * hh + 2] = fmaf(p[hh], va.z, oa[8 * hh + 2]);
                oa[8 * hh + 3] = fmaf(p[hh], va.w, oa[8 * hh + 3]);
                oa[8 * hh + 4] = fmaf(p[hh], vb.x, oa[8 * hh + 4]);
                oa[8 * hh + 5] = fmaf(p[hh], vb.y, oa[8 * hh + 5]);
                oa[8 * hh + 6] = fmaf(p[hh], vb.z, oa[8 * hh + 6]);
                oa[8 * hh + 7] = fmaf(p[hh], vb.w, oa[8 * hh + 7]);
            }
        }

        float rl[NHEAD];
#pragma unroll
        for (int hh = 0; hh < NHEAD; hh++) rl[hh] = 1.0f / l[hh];
#pragma unroll
        for (int c = 0; c < D_MODEL; c++) oa[c] *= rl[c >> 3];

        // ----- out proj + residual + LN1 -----
        float t1[D_MODEL];
#pragma unroll
        for (int c = 0; c < D_MODEL; c++)
            t1[c] = h[c] + dot32(sw + L_OPW + c * 32, oa) + sw[L_OPB + c];
        ln32(t1, sw + L_G1, sw + L_B1, h);

        // ----- FF (exact gelu) -----
        float f2[D_MODEL];
#pragma unroll
        for (int c = 0; c < D_MODEL; c++) f2[c] = sw[L_BB2 + c];
#pragma unroll 1
        for (int f = 0; f < DFF; f++) {
            float t = dot32(sw + L_W1 + f * 32, h) + sw[L_BB1 + f];
            float gl = 0.5f * t * (1.0f + erff(t * 0.70710678118654752440f));
            const float4* wp = reinterpret_cast<const float4*>(sw + L_W2T + f * 32);
#pragma unroll
            for (int i = 0; i < 8; i++) {
                float4 wv = wp[i];
                f2[4 * i + 0] = fmaf(gl, wv.x, f2[4 * i + 0]);
                f2[4 * i + 1] = fmaf(gl, wv.y, f2[4 * i + 1]);
                f2[4 * i + 2] = fmaf(gl, wv.z, f2[4 * i + 2]);
                f2[4 * i + 3] = fmaf(gl, wv.w, f2[4 * i + 3]);
            }
        }
        float t2[D_MODEL];
#pragma unroll
        for (int c = 0; c < D_MODEL; c++) t2[c] = h[c] + f2[c];
        ln32(t2, sw + L_G2, sw + L_B2, h);
    }

    // ---------------- final LN + head ----------------
    __syncthreads();
    if (tid < 32) { sw[H_NOG + tid] = nog[tid]; sw[H_NOB + tid] = nob[tid]; }
    for (int i = tid; i < HOUT * 32; i += 256) sw[H_HW + i] = hw[i];
    if (tid < HOUT) sw[H_HB + tid] = hb[tid];
    __syncthreads();

    float hn[D_MODEL];
    ln32(h, sw + H_NOG, sw + H_NOB, hn);
    float* op = out + (size_t)g * HOUT;
#pragma unroll 1
    for (int c = 0; c < HOUT; c++)
        op[c] = dot32(sw + H_HW + c * 32, hn) + sw[H_HB + c];
}

extern "C" void kernel_launch(void* const* d_in, const int* in_sizes, int n_in,
                              void* d_out, int out_size) {
    const float* x    = (const float*)d_in[0];
    const int*   lays = (const int*)d_in[1];
    const float* fpw  = (const float*)d_in[2];
    const float* fpb  = (const float*)d_in[3];
    const float* lemb = (const float*)d_in[4];
    const float* fB   = (const float*)d_in[5];
    const float* ipw  = (const float*)d_in[6];
    const float* ipb  = (const float*)d_in[7];
    const float* opw  = (const float*)d_in[8];
    const float* opb  = (const float*)d_in[9];
    const float* g1   = (const float*)d_in[10];
    const float* b1   = (const float*)d_in[11];
    const float* w1   = (const float*)d_in[12];
    const float* bb1  = (const float*)d_in[13];
    const float* w2   = (const float*)d_in[14];
    const float* bb2  = (const float*)d_in[15];
    const float* g2   = (const float*)d_in[16];
    const float* b2   = (const float*)d_in[17];
    const float* nog  = (const float*)d_in[18];
    const float* nob  = (const float*)d_in[19];
    const float* hw   = (const float*)d_in[20];
    const float* hb   = (const float*)d_in[21];
    float* out = (float*)d_out;

    const int tokens = in_sizes[0] / INDIM;
    const int grid = tokens / WIN;

    cudaFuncSetAttribute(spai_kernel, cudaFuncAttributeMaxDynamicSharedMemorySize, SMEM_BYTES);
    spai_kernel<<<grid, 256, SMEM_BYTES>>>(x, lays, fpw, fpb, lemb, fB, ipw, ipb, opw, opb,
                                           g1, b1, w1, bb1, w2, bb2, g2, b2, nog, nob, hw, hb,
                                           out);
}

// round 4
// speedup vs baseline: 1.1848x; 1.1848x over previous
#include <cuda_runtime.h>
#include <math.h>

#define D_MODEL 32
#define NHEAD 4
#define WIN 256
#define DFF 64
#define INDIM 58
#define HOUT 25
#define NLAYER 4

// ---- shared memory layout (floats) ----
#define L_IPW  0      // 96*32
#define L_IPB  3072   // 96
#define L_OPW  3168   // 32*32
#define L_OPB  4192   // 32
#define L_G1   4224
#define L_B1   4256
#define L_W1   4288   // 64*32
#define L_BB1  6336   // 64
#define L_W2T  6400   // 64*32 (transposed lin2_w)
#define L_BB2  8448
#define L_G2   8480
#define L_B2   8512

// embedding overlay
#define E_FPW  0      // 32*58
#define E_FPB  1856
#define E_LEMB 1888   // 12*32
#define E_FB   2272   // 3*16

// head overlay
#define H_NOG  0
#define H_NOB  32
#define H_HW   64     // 25*32
#define H_HB   864

#define KV_STRIDE 36
#define OFF_K  8544
#define OFF_V  (OFF_K + WIN*KV_STRIDE)
#define SMEM_FLOATS (OFF_V + WIN*KV_STRIDE)
#define SMEM_BYTES (SMEM_FLOATS * 4)

typedef unsigned long long u64;

__device__ __forceinline__ u64 pk2(float lo, float hi) {
    u64 r; asm("mov.b64 %0,{%1,%2};" : "=l"(r) : "f"(lo), "f"(hi)); return r;
}
__device__ __forceinline__ void upk2(u64 p, float& lo, float& hi) {
    asm("mov.b64 {%0,%1},%2;" : "=f"(lo), "=f"(hi) : "l"(p));
}
__device__ __forceinline__ u64 ffma2(u64 a, u64 b, u64 c) {
    u64 d; asm("fma.rn.f32x2 %0,%1,%2,%3;" : "=l"(d) : "l"(a), "l"(b), "l"(c)); return d;
}
__device__ __forceinline__ u64 fmul2(u64 a, u64 b) {
    u64 d; asm("mul.rn.f32x2 %0,%1,%2;" : "=l"(d) : "l"(a), "l"(b)); return d;
}
__device__ __forceinline__ u64 fadd2(u64 a, u64 b) {
    u64 d; asm("add.rn.f32x2 %0,%1,%2;" : "=l"(d) : "l"(a), "l"(b)); return d;
}
__device__ __forceinline__ float hsum2(u64 p) { float lo, hi; upk2(p, lo, hi); return lo + hi; }
__device__ __forceinline__ u64 dup2(float v) { return pk2(v, v); }

// dot of one 32-float weight row against two packed-16 token vectors
__device__ __forceinline__ void dot32x2(const float* __restrict__ w,
                                        const u64  va[16], const u64 vb[16],
                                        float& ra, float& rb) {
    const ulonglong2* wp = reinterpret_cast<const ulonglong2*>(w);
    u64 a0 = 0, a1 = 0, b0 = 0, b1 = 0;
#pragma unroll
    for (int i = 0; i < 8; i++) {
        ulonglong2 wv = wp[i];
        a0 = ffma2(wv.x, va[2 * i], a0);
        a1 = ffma2(wv.y, va[2 * i + 1], a1);
        b0 = ffma2(wv.x, vb[2 * i], b0);
        b1 = ffma2(wv.y, vb[2 * i + 1], b1);
    }
    ra = hsum2(fadd2(a0, a1));
    rb = hsum2(fadd2(b0, b1));
}

// packed layernorm over 16 pairs
__device__ __forceinline__ void ln32p(const u64 v[16], const float* __restrict__ g,
                                      const float* __restrict__ b, u64 o[16]) {
    u64 s = 0;
#pragma unroll
    for (int i = 0; i < 16; i++) s = fadd2(s, v[i]);
    float m = hsum2(s) * 0.03125f;
    u64 mneg = dup2(-m);
    u64 q = 0;
#pragma unroll
    for (int i = 0; i < 16; i++) { u64 d = fadd2(v[i], mneg); o[i] = d; q = ffma2(d, d, q); }
    float var = hsum2(q) * 0.03125f;
    u64 iv = dup2(rsqrtf(var + 1e-5f));
    const ulonglong2* gp = reinterpret_cast<const ulonglong2*>(g);
    const ulonglong2* bp = reinterpret_cast<const ulonglong2*>(b);
#pragma unroll
    for (int i = 0; i < 8; i++) {
        ulonglong2 gg = gp[i], bb = bp[i];
        o[2 * i]     = ffma2(fmul2(o[2 * i], iv), gg.x, bb.x);
        o[2 * i + 1] = ffma2(fmul2(o[2 * i + 1], iv), gg.y, bb.y);
    }
}

__device__ __forceinline__ void embed_token(const float* __restrict__ sw,
                                            const float* __restrict__ xp,
                                            int lay, float h[D_MODEL]) {
    const float p0 = xp[0], p1 = xp[1], p2 = xp[2];
#pragma unroll
    for (int c = 0; c < D_MODEL; c++) h[c] = sw[E_FPB + c] + sw[E_LEMB + lay * 32 + c];
#pragma unroll 1
    for (int k = 0; k < INDIM; k++) {
        float xk = __ldg(xp + k);
#pragma unroll
        for (int c = 0; c < D_MODEL; c++) h[c] = fmaf(xk, sw[E_FPW + c * INDIM + k], h[c]);
    }
#pragma unroll
    for (int j = 0; j < 16; j++) {
        float pr = 6.28318530717958647692f *
                   (p0 * sw[E_FB + j] + p1 * sw[E_FB + 16 + j] + p2 * sw[E_FB + 32 + j]);
        float sn, cs;
        sincosf(pr, &sn, &cs);
        h[j] += sn;
        h[j + 16] += cs;
    }
}

__global__ void __launch_bounds__(128, 2) spai_kernel(
    const float* __restrict__ x, const int* __restrict__ layers,
    const float* __restrict__ fpw, const float* __restrict__ fpb,
    const float* __restrict__ lemb, const float* __restrict__ fB,
    const float* __restrict__ ipw, const float* __restrict__ ipb,
    const float* __restrict__ opw, const float* __restrict__ opb,
    const float* __restrict__ g1, const float* __restrict__ b1,
    const float* __restrict__ w1, const float* __restrict__ bb1,
    const float* __restrict__ w2, const float* __restrict__ bb2,
    const float* __restrict__ g2, const float* __restrict__ b2,
    const float* __restrict__ nog, const float* __restrict__ nob,
    const float* __restrict__ hw, const float* __restrict__ hb,
    float* __restrict__ out)
{
    extern __shared__ float sw[];
    float* ks = sw + OFF_K;
    float* vs = sw + OFF_V;
    const int tid = threadIdx.x;
    const int rowA = 2 * tid, rowB = 2 * tid + 1;         // two token rows per thread
    const long long ga = (long long)blockIdx.x * WIN + rowA;
    const long long gb = ga + 1;

    // ---------------- embedding weights ----------------
    for (int i = tid; i < 32 * INDIM; i += 128) sw[E_FPW + i] = fpw[i];
    if (tid < 32) sw[E_FPB + tid] = fpb[tid];
    for (int i = tid; i < 12 * 32; i += 128) sw[E_LEMB + i] = lemb[i];
    if (tid < 48) sw[E_FB + tid] = fB[tid];
    __syncthreads();

    // ---------------- embedding (2 tokens) ----------------
    float hsa[D_MODEL], hsb[D_MODEL];
    embed_token(sw, x + (size_t)ga * INDIM, layers[ga], hsa);
    embed_token(sw, x + (size_t)gb * INDIM, layers[gb], hsb);

    u64 hA[16], hB[16];
#pragma unroll
    for (int i = 0; i < 16; i++) { hA[i] = pk2(hsa[2 * i], hsa[2 * i + 1]); hB[i] = pk2(hsb[2 * i], hsb[2 * i + 1]); }

    // ---------------- transformer layers ----------------
    for (int li = 0; li < NLAYER; li++) {
        __syncthreads();
        for (int i = tid; i < 3072; i += 128) sw[L_IPW + i] = ipw[li * 3072 + i];
        if (tid < 96)  sw[L_IPB + tid] = ipb[li * 96 + tid];
        for (int i = tid; i < 1024; i += 128) sw[L_OPW + i] = opw[li * 1024 + i];
        if (tid < 32) {
            sw[L_OPB + tid] = opb[li * 32 + tid];
            sw[L_G1 + tid]  = g1[li * 32 + tid];
            sw[L_B1 + tid]  = b1[li * 32 + tid];
            sw[L_BB2 + tid] = bb2[li * 32 + tid];
            sw[L_G2 + tid]  = g2[li * 32 + tid];
            sw[L_B2 + tid]  = b2[li * 32 + tid];
        }
        for (int i = tid; i < 2048; i += 128) sw[L_W1 + i] = w1[li * 2048 + i];
        if (tid < 64)  sw[L_BB1 + tid] = bb1[li * 64 + tid];
        for (int i = tid; i < 2048; i += 128) {
            int c = i >> 6, f = i & 63;
            sw[L_W2T + f * 32 + c] = w2[li * 2048 + i];
        }
        __syncthreads();

        // ----- QKV -----
        const float rs = 0.35355339059327376220f;  // 1/sqrt(8) folded into q
        u64 qA[16], qB[16];
#pragma unroll 2
        for (int o = 0; o < 32; o += 2) {
            float a0, b0, a1, b1;
            dot32x2(sw + L_IPW + o * 32, hA, hB, a0, b0);
            dot32x2(sw + L_IPW + (o + 1) * 32, hA, hB, a1, b1);
            float i0 = sw[L_IPB + o], i1 = sw[L_IPB + o + 1];
            qA[o >> 1] = pk2((a0 + i0) * rs, (a1 + i1) * rs);
            qB[o >> 1] = pk2((b0 + i0) * rs, (b1 + i1) * rs);
        }
#pragma unroll 1
        for (int o = 32; o < 96; o += 4) {
            float ta[4], tb[4];
#pragma unroll
            for (int u = 0; u < 4; u++) {
                dot32x2(sw + L_IPW + (o + u) * 32, hA, hB, ta[u], tb[u]);
                float bi = sw[L_IPB + o + u];
                ta[u] += bi; tb[u] += bi;
            }
            float* dst = (o < 64) ? ks : vs;
            int c = (o < 64) ? (o - 32) : (o - 64);
            *reinterpret_cast<float4*>(dst + rowA * KV_STRIDE + c) = make_float4(ta[0], ta[1], ta[2], ta[3]);
            *reinterpret_cast<float4*>(dst + rowB * KV_STRIDE + c) = make_float4(tb[0], tb[1], tb[2], tb[3]);
        }
        __syncthreads();

        // ----- attention -----
        u64 oaA[16], oaB[16];
#pragma unroll
        for (int i = 0; i < 16; i++) { oaA[i] = 0; oaB[i] = 0; }
        float la[NHEAD] = {0.f, 0.f, 0.f, 0.f};
        float lb[NHEAD] = {0.f, 0.f, 0.f, 0.f};

#pragma unroll 2
        for (int j = 0; j < WIN; j++) {
            const ulonglong2* kp = reinterpret_cast<const ulonglong2*>(ks + j * KV_STRIDE);
            const ulonglong2* vp = reinterpret_cast<const ulonglong2*>(vs + j * KV_STRIDE);
#pragma unroll
            for (int hh = 0; hh < NHEAD; hh++) {
                ulonglong2 kA = kp[2 * hh], kB = kp[2 * hh + 1];
                u64 sa = fmul2(kA.x, qA[4 * hh]);
                sa = ffma2(kA.y, qA[4 * hh + 1], sa);
                sa = ffma2(kB.x, qA[4 * hh + 2], sa);
                sa = ffma2(kB.y, qA[4 * hh + 3], sa);
                u64 sb = fmul2(kA.x, qB[4 * hh]);
                sb = ffma2(kA.y, qB[4 * hh + 1], sb);
                sb = ffma2(kB.x, qB[4 * hh + 2], sb);
                sb = ffma2(kB.y, qB[4 * hh + 3], sb);
                float pa = __expf(hsum2(sa));
                float pb = __expf(hsum2(sb));
                la[hh] += pa; lb[hh] += pb;
                u64 ppa = dup2(pa), ppb = dup2(pb);
                ulonglong2 vA = vp[2 * hh], vB = vp[2 * hh + 1];
                oaA[4 * hh]     = ffma2(ppa, vA.x, oaA[4 * hh]);
                oaA[4 * hh + 1] = ffma2(ppa, vA.y, oaA[4 * hh + 1]);
                oaA[4 * hh + 2] = ffma2(ppa, vB.x, oaA[4 * hh + 2]);
                oaA[4 * hh + 3] = ffma2(ppa, vB.y, oaA[4 * hh + 3]);
                oaB[4 * hh]     = ffma2(ppb, vA.x, oaB[4 * hh]);
                oaB[4 * hh + 1] = ffma2(ppb, vA.y, oaB[4 * hh + 1]);
                oaB[4 * hh + 2] = ffma2(ppb, vB.x, oaB[4 * hh + 2]);
                oaB[4 * hh + 3] = ffma2(ppb, vB.y, oaB[4 * hh + 3]);
            }
        }

#pragma unroll
        for (int hh = 0; hh < NHEAD; hh++) {
            u64 rla = dup2(1.0f / la[hh]), rlb = dup2(1.0f / lb[hh]);
#pragma unroll
            for (int p = 0; p < 4; p++) {
                oaA[4 * hh + p] = fmul2(oaA[4 * hh + p], rla);
                oaB[4 * hh + p] = fmul2(oaB[4 * hh + p], rlb);
            }
        }

        // ----- out proj + residual + LN1 -----
        u64 t1a[16], t1b[16];
#pragma unroll 2
        for (int c = 0; c < 32; c += 2) {
            float x0a, x0b, x1a, x1b;
            dot32x2(sw + L_OPW + c * 32, oaA, oaB, x0a, x0b);
            dot32x2(sw + L_OPW + (c + 1) * 32, oaA, oaB, x1a, x1b);
            float o0 = sw[L_OPB + c], o1 = sw[L_OPB + c + 1];
            t1a[c >> 1] = fadd2(hA[c >> 1], pk2(x0a + o0, x1a + o1));
            t1b[c >> 1] = fadd2(hB[c >> 1], pk2(x0b + o0, x1b + o1));
        }
        ln32p(t1a, sw + L_G1, sw + L_B1, hA);
        ln32p(t1b, sw + L_G1, sw + L_B1, hB);

        // ----- FF -----
        u64 f2a[16], f2b[16];
        {
            const ulonglong2* bp = reinterpret_cast<const ulonglong2*>(sw + L_BB2);
#pragma unroll
            for (int i = 0; i < 8; i++) {
                ulonglong2 bb = bp[i];
                f2a[2 * i] = bb.x; f2a[2 * i + 1] = bb.y;
                f2b[2 * i] = bb.x; f2b[2 * i + 1] = bb.y;
            }
        }
#pragma unroll 1
        for (int f = 0; f < DFF; f++) {
            float ta, tb;
            dot32x2(sw + L_W1 + f * 32, hA, hB, ta, tb);
            float bi = sw[L_BB1 + f];
            ta += bi; tb += bi;
            float gla = 0.5f * ta * (1.0f + erff(ta * 0.70710678118654752440f));
            float glb = 0.5f * tb * (1.0f + erff(tb * 0.70710678118654752440f));
            u64 gga = dup2(gla), ggb = dup2(glb);
            const ulonglong2* wp = reinterpret_cast<const ulonglong2*>(sw + L_W2T + f * 32);
#pragma unroll
            for (int i = 0; i < 8; i++) {
                ulonglong2 w2v = wp[i];
                f2a[2 * i]     = ffma2(gga, w2v.x, f2a[2 * i]);
                f2a[2 * i + 1] = ffma2(gga, w2v.y, f2a[2 * i + 1]);
                f2b[2 * i]     = ffma2(ggb, w2v.x, f2b[2 * i]);
                f2b[2 * i + 1] = ffma2(ggb, w2v.y, f2b[2 * i + 1]);
            }
        }
        u64 t2a[16], t2b[16];
#pragma unroll
        for (int i = 0; i < 16; i++) { t2a[i] = fadd2(hA[i], f2a[i]); t2b[i] = fadd2(hB[i], f2b[i]); }
        ln32p(t2a, sw + L_G2, sw + L_B2, hA);
        ln32p(t2b, sw + L_G2, sw + L_B2, hB);
    }

    // ---------------- final LN + head ----------------
    __syncthreads();
    if (tid < 32) { sw[H_NOG + tid] = nog[tid]; sw[H_NOB + tid] = nob[tid]; }
    for (int i = tid; i < HOUT * 32; i += 128) sw[H_HW + i] = hw[i];
    if (tid < HOUT) sw[H_HB + tid] = hb[tid];
    __syncthreads();

    u64 na[16], nb[16];
    ln32p(hA, sw + H_NOG, sw + H_NOB, na);
    ln32p(hB, sw + H_NOG, sw + H_NOB, nb);

    float* outA = out + (size_t)ga * HOUT;
    float* outB = out + (size_t)gb * HOUT;
#pragma unroll 1
    for (int c = 0; c < HOUT; c++) {
        float ta, tb;
        dot32x2(sw + H_HW + c * 32, na, nb, ta, tb);
        float bi = sw[H_HB + c];
        outA[c] = ta + bi;
        outB[c] = tb + bi;
    }
}

extern "C" void kernel_launch(void* const* d_in, const int* in_sizes, int n_in,
                              void* d_out, int out_size) {
    const float* x    = (const float*)d_in[0];
    const int*   lays = (const int*)d_in[1];
    const float* fpw  = (const float*)d_in[2];
    const float* fpb  = (const float*)d_in[3];
    const float* lemb = (const float*)d_in[4];
    const float* fB   = (const float*)d_in[5];
    const float* ipw  = (const float*)d_in[6];
    const float* ipb  = (const float*)d_in[7];
    const float* opw  = (const float*)d_in[8];
    const float* opb  = (const float*)d_in[9];
    const float* g1   = (const float*)d_in[10];
    const float* b1   = (const float*)d_in[11];
    const float* w1   = (const float*)d_in[12];
    const float* bb1  = (const float*)d_in[13];
    const float* w2   = (const float*)d_in[14];
    const float* bb2  = (const float*)d_in[15];
    const float* g2   = (const float*)d_in[16];
    const float* b2   = (const float*)d_in[17];
    const float* nog  = (const float*)d_in[18];
    const float* nob  = (const float*)d_in[19];
    const float* hw   = (const float*)d_in[20];
    const float* hb   = (const float*)d_in[21];
    float* out = (float*)d_out;

    const int tokens = in_sizes[0] / INDIM;
    const int grid = tokens / WIN;

    cudaFuncSetAttribute(spai_kernel, cudaFuncAttributeMaxDynamicSharedMemorySize, SMEM_BYTES);
    spai_kernel<<<grid, 128, SMEM_BYTES>>>(x, lays, fpw, fpb, lemb, fB, ipw, ipb, opw, opb,
                                           g1, b1, w1, bb1, w2, bb2, g2, b2, nog, nob, hw, hb,
                                           out);
}